// round 4
// baseline (speedup 1.0000x reference)
#include <cuda_runtime.h>
#include <cuda_bf16.h>

#define NUM_NODES   4000000
#define NUM_PHYS    3000000
#define NUM_MOVABLE 2500000
#define NB          1024
#define NBINS       (NB * NB)

// 4 MB density map scratch (device global: allocation-free per harness rules)
__device__ float g_pmap[NBINS];

__global__ __launch_bounds__(256) void zero_pmap_kernel() {
    int i = blockIdx.x * blockDim.x + threadIdx.x;
    reinterpret_cast<float4*>(g_pmap)[i] = make_float4(0.f, 0.f, 0.f, 0.f);
}

// ---------------------------------------------------------------------------
// Scatter: 3M phys nodes add weighted overlap into the bin map.
// Data ranges guarantee xmax,ymax < 1024.0 strictly, so overlap with any bin
// index >= NB is <= 0 and fmaxf(...,0) kills it: no bounds branches needed.
// Only the atomic itself is predicated on v != 0.
// ---------------------------------------------------------------------------
__global__ __launch_bounds__(256) void scatter_kernel(
    const float* __restrict__ pos,
    const float* __restrict__ nsx,
    const float* __restrict__ nsy,
    const int*   __restrict__ pw)
{
    int i = blockIdx.x * blockDim.x + threadIdx.x;
    if (i >= NUM_PHYS) return;

    float sx = __ldg(nsx + i);
    float sy = __ldg(nsy + i);
    float px = __ldg(pos + i);
    float py = __ldg(pos + NUM_NODES + i);
    int   w  = __ldg(pw + i);

    float hx = 0.5f * fmaxf(1.414f, sx);   // bsx = 1.0
    float hy = 0.5f * fmaxf(1.414f, sy);
    float cx = px + 0.5f * sx;
    float cy = py + 0.5f * sy;
    float xmin = cx - hx, xmax = cx + hx;
    float ymin = cy - hy, ymax = cy + hy;
    float dens = (float)w / (4.0f * hx * hy);

    int bxl = min(max((int)floorf(xmin), 0), NB - 1);
    int byl = min(max((int)floorf(ymin), 0), NB - 1);

    float oy[4], ox[4];
#pragma unroll
    for (int d = 0; d < 4; d++) {
        float byf = (float)(byl + d);
        oy[d] = fmaxf(fminf(ymax, byf + 1.0f) - fmaxf(ymin, byf), 0.0f);
        float bxf = (float)(bxl + d);
        ox[d] = fmaxf(fminf(xmax, bxf + 1.0f) - fmaxf(xmin, bxf), 0.0f);
    }

#pragma unroll
    for (int di = 0; di < 4; di++) {
        float dox = dens * ox[di];
        // clamp memory row only; weight is already 0 for any OOB bin
        float* row = g_pmap + min(bxl + di, NB - 1) * NB;
#pragma unroll
        for (int dj = 0; dj < 4; dj++) {
            float v = dox * oy[dj];
            if (v != 0.0f)
                atomicAdd(row + min(byl + dj, NB - 1), v);
        }
    }
}

// ---------------------------------------------------------------------------
// Gather: 2.5M movable nodes sum adj-weighted overlaps. Fully branchless:
// issue all 16 L2 loads up front (MLP=16), combine after.
// ---------------------------------------------------------------------------
__global__ __launch_bounds__(256) void gather_kernel(
    const float* __restrict__ pos,
    const float* __restrict__ nsx,
    const float* __restrict__ nsy,
    float*       __restrict__ out)
{
    int i = blockIdx.x * blockDim.x + threadIdx.x;
    if (i >= NUM_MOVABLE) return;

    float mx  = __ldg(pos + i);
    float my  = __ldg(pos + NUM_NODES + i);
    float msx = __ldg(nsx + i);
    float msy = __ldg(nsy + i);
    float xmax = mx + msx;
    float ymax = my + msy;

    int bxl = min(max((int)floorf(mx), 0), NB - 1);
    int byl = min(max((int)floorf(my), 0), NB - 1);

    float ox[4], oy[4];
    int   col[4];
#pragma unroll
    for (int d = 0; d < 4; d++) {
        float bxf = (float)(bxl + d);
        ox[d] = fmaxf(fminf(xmax, bxf + 1.0f) - fmaxf(mx, bxf), 0.0f);
        float byf = (float)(byl + d);
        oy[d] = fmaxf(fminf(ymax, byf + 1.0f) - fmaxf(my, byf), 0.0f);
        col[d] = min(byl + d, NB - 1);
    }

    // Batch all 16 loads (clamped addresses; zero weights kill OOB terms)
    float p[4][4];
#pragma unroll
    for (int di = 0; di < 4; di++) {
        const float* row = g_pmap + min(bxl + di, NB - 1) * NB;
#pragma unroll
        for (int dj = 0; dj < 4; dj++)
            p[di][dj] = __ldg(row + col[dj]);
    }

    float area = 0.0f;
#pragma unroll
    for (int di = 0; di < 4; di++) {
#pragma unroll
        for (int dj = 0; dj < 4; dj++) {
            // adj = clip(pmap * 0.5, 0.4, 2.5); bsx*bsy == 1
            float adj = fminf(fmaxf(p[di][dj] * 0.5f, 0.4f), 2.5f);
            area = fmaf(ox[di] * oy[dj], adj, area);
        }
    }
    out[i] = area;
}

extern "C" void kernel_launch(void* const* d_in, const int* in_sizes, int n_in,
                              void* d_out, int out_size)
{
    const float* pos = (const float*)d_in[0];
    const float* nsx = (const float*)d_in[1];
    const float* nsy = (const float*)d_in[2];
    const int*   pw  = (const int*)  d_in[3];
    float* out = (float*)d_out;

    zero_pmap_kernel<<<NBINS / 4 / 256, 256>>>();
    scatter_kernel<<<(NUM_PHYS + 255) / 256, 256>>>(pos, nsx, nsy, pw);
    gather_kernel<<<(NUM_MOVABLE + 255) / 256, 256>>>(pos, nsx, nsy, out);
}

// round 5
// speedup vs baseline: 1.4672x; 1.4672x over previous
#include <cuda_runtime.h>
#include <cuda_bf16.h>

#define NUM_NODES   4000000
#define NUM_PHYS    3000000
#define NUM_MOVABLE 2500000
#define NB          1024
#define NBINS       (NB * NB)

// 4 MB density map + 4 pad floats: even-aligned v2 REDs may touch one slot
// past the last bin of the last row with weight 0.0 (harmless, never read).
__device__ float g_pmap[NBINS + 4];

__global__ __launch_bounds__(256) void zero_pmap_kernel() {
    int i = blockIdx.x * blockDim.x + threadIdx.x;
    reinterpret_cast<float4*>(g_pmap)[i] = make_float4(0.f, 0.f, 0.f, 0.f);
}

__device__ __forceinline__ void red_v2(float* p, float a, float b) {
    asm volatile("red.global.v2.f32.add [%0], {%1, %2};"
                 :: "l"(p), "f"(a), "f"(b) : "memory");
}

// ---------------------------------------------------------------------------
// Scatter: 3M phys nodes. Nonzero y-bins are contiguous (byl..byl+2);
// cover them with even-aligned v2 vector reductions (1 RED.64 per live pair).
// ---------------------------------------------------------------------------
__global__ __launch_bounds__(256) void scatter_kernel(
    const float* __restrict__ pos,
    const float* __restrict__ nsx,
    const float* __restrict__ nsy,
    const int*   __restrict__ pw)
{
    int i = blockIdx.x * blockDim.x + threadIdx.x;
    if (i >= NUM_PHYS) return;

    float sx = nsx[i];
    float sy = nsy[i];
    float hx = 0.5f * fmaxf(1.414f, sx);   // bsx = bsy = 1.0
    float hy = 0.5f * fmaxf(1.414f, sy);
    float cx = pos[i]             + 0.5f * sx;
    float cy = pos[NUM_NODES + i] + 0.5f * sy;
    float xmin = cx - hx, xmax = cx + hx;
    float ymin = cy - hy, ymax = cy + hy;
    float dens = (float)pw[i] / (4.0f * hx * hy);

    int bxl  = min(max((int)floorf(xmin), 0), NB - 1);
    int byl  = min(max((int)floorf(ymin), 0), NB - 1);
    int byl0 = byl & ~1;   // even-aligned window start; nonzero bins byl..byl+2
                           // are inside [byl0, byl0+3]

    float oy[4];
#pragma unroll
    for (int k = 0; k < 4; k++) {
        float byf = (float)(byl0 + k);
        oy[k] = fmaxf(fminf(ymax, byf + 1.0f) - fmaxf(ymin, byf), 0.0f);
    }

#pragma unroll
    for (int di = 0; di < 4; di++) {
        int bx = bxl + di;
        if (bx >= NB) break;
        float bxf = (float)bx;
        float ox = fmaxf(fminf(xmax, bxf + 1.0f) - fmaxf(xmin, bxf), 0.0f);
        if (ox <= 0.0f) continue;             // adding 0 == skipping
        float dox = dens * ox;
        float* row = g_pmap + bx * NB + byl0; // 8B-aligned (byl0 even)
        float v0 = dox * oy[0], v1 = dox * oy[1];
        float v2 = dox * oy[2], v3 = dox * oy[3];
        if (v0 != 0.0f || v1 != 0.0f) red_v2(row,     v0, v1);
        if (v2 != 0.0f || v3 != 0.0f) red_v2(row + 2, v2, v3);
    }
}

// ---------------------------------------------------------------------------
// Gather (exact R1 structure — proven fastest): early-exit on zero overlap,
// load only live bins.
// ---------------------------------------------------------------------------
__global__ __launch_bounds__(256) void gather_kernel(
    const float* __restrict__ pos,
    const float* __restrict__ nsx,
    const float* __restrict__ nsy,
    float*       __restrict__ out)
{
    int i = blockIdx.x * blockDim.x + threadIdx.x;
    if (i >= NUM_MOVABLE) return;

    float mx  = pos[i];
    float my  = pos[NUM_NODES + i];
    float msx = nsx[i];
    float msy = nsy[i];
    float xmax = mx + msx;
    float ymax = my + msy;

    int bxl = min(max((int)floorf(mx), 0), NB - 1);
    int byl = min(max((int)floorf(my), 0), NB - 1);

    float oy[4];
#pragma unroll
    for (int dj = 0; dj < 4; dj++) {
        float byf = (float)(byl + dj);
        oy[dj] = fmaxf(fminf(ymax, byf + 1.0f) - fmaxf(my, byf), 0.0f);
    }

    float area = 0.0f;
#pragma unroll
    for (int di = 0; di < 4; di++) {
        int bx = bxl + di;
        if (bx >= NB) break;
        float bxf = (float)bx;
        float ox = fmaxf(fminf(xmax, bxf + 1.0f) - fmaxf(mx, bxf), 0.0f);
        if (ox <= 0.0f) continue;
        const float* row = g_pmap + bx * NB + byl;
#pragma unroll
        for (int dj = 0; dj < 4; dj++) {
            if (byl + dj >= NB) break;
            float o = ox * oy[dj];
            if (o != 0.0f) {
                // adj = clip(pmap * 0.5, 0.4, 2.5); bsx*bsy == 1
                float adj = fminf(fmaxf(row[dj] * 0.5f, 0.4f), 2.5f);
                area += o * adj;
            }
        }
    }
    out[i] = area;
}

extern "C" void kernel_launch(void* const* d_in, const int* in_sizes, int n_in,
                              void* d_out, int out_size)
{
    const float* pos = (const float*)d_in[0];
    const float* nsx = (const float*)d_in[1];
    const float* nsy = (const float*)d_in[2];
    const int*   pw  = (const int*)  d_in[3];
    float* out = (float*)d_out;

    zero_pmap_kernel<<<(NBINS + 4) / 4 / 256, 256>>>();
    scatter_kernel<<<(NUM_PHYS + 255) / 256, 256>>>(pos, nsx, nsy, pw);
    gather_kernel<<<(NUM_MOVABLE + 255) / 256, 256>>>(pos, nsx, nsy, out);
}